// round 4
// baseline (speedup 1.0000x reference)
#include <cuda_runtime.h>
#include <math.h>

// Problem constants
#define XDIM 32
#define UDIM 8
#define ADIM 24
#define TT   128
#define BB   256
#define G    2          // batch elements per CTA
#define NTHREADS 256
#define EPSV 1e-6f

enum { ACT_RELU = 0, ACT_ID = 1, ACT_SIG = 2, ACT_AM = 3 };

struct __align__(16) Smem {
    float qm[G][32];            // posterior mean (state)
    float pm[G][32];            // prior mean
    float qc[G][32][32];        // posterior cov (state)
    float pc[G][32][32];        // prior cov
    float h1[G][256];
    float h2[G][256];
    float Am[G][32][33];        // padded (read column-wise)
    float Bm[G][32][8];
    float Cm[G][24][33];        // padded
    float nx[G][32];
    float na[G][24];
    float T1[G][32][32];        // Am @ qc
    float T2[G][24][32];        // Cm @ pc
    float T3[G][32][24];        // pc @ Cm^T
    float Gmat[G][32][24];      // Kalman gain
    float P[G][32][33];         // raw cov before symmetrize (padded)
    float Saug[G][24][48];      // [S | I] for Gauss-Jordan
    float rowbuf[G][48];
    float colbuf[G][24];
    float innov[G][24];
    float uvec[G][8];
    float avec[G][24];
    float pivinv[G];
};

// out[g][r] = act(bias[r] + sum_k W[r*K+k] * in_g[k])
// 4 lanes split K, 8 rows per warp. float4 weight loads (fully coalesced by
// sectors), h reads are quad-broadcast LDS.128. 2 shuffle rounds per row.
template<int K, int ACT>
__device__ __forceinline__ void matvec_g2(
    const float* __restrict__ W, const float* __restrict__ bias,
    const float* in0, const float* in1,
    float* out0, float* out1,
    int R, int pitch, float alphav)
{
    const int tid  = threadIdx.x;
    const int lane = tid & 31;
    const int warp = tid >> 5;
    const int sub  = lane & 3;   // k-split within quad
    const int rloc = lane >> 2;  // 0..7 row within warp
    constexpr int J = K / 16;    // float4-steps per lane

    for (int rbase = warp * 8; rbase < R; rbase += 64) {
        const int r = rbase + rloc;
        const float4* Wr = reinterpret_cast<const float4*>(W) + (size_t)r * (K / 4);
        float a00 = 0.f, a01 = 0.f, a02 = 0.f, a03 = 0.f;
        float a10 = 0.f, a11 = 0.f, a12 = 0.f, a13 = 0.f;
        #pragma unroll
        for (int j = 0; j < J; ++j) {
            const float4 w  = Wr[j * 4 + sub];
            const float4 x0 = *reinterpret_cast<const float4*>(in0 + (j * 4 + sub) * 4);
            const float4 x1 = *reinterpret_cast<const float4*>(in1 + (j * 4 + sub) * 4);
            a00 = fmaf(w.x, x0.x, a00); a01 = fmaf(w.y, x0.y, a01);
            a02 = fmaf(w.z, x0.z, a02); a03 = fmaf(w.w, x0.w, a03);
            a10 = fmaf(w.x, x1.x, a10); a11 = fmaf(w.y, x1.y, a11);
            a12 = fmaf(w.z, x1.z, a12); a13 = fmaf(w.w, x1.w, a13);
        }
        float s0 = (a00 + a01) + (a02 + a03);
        float s1 = (a10 + a11) + (a12 + a13);
        s0 += __shfl_xor_sync(0xffffffffu, s0, 1);
        s0 += __shfl_xor_sync(0xffffffffu, s0, 2);
        s1 += __shfl_xor_sync(0xffffffffu, s1, 1);
        s1 += __shfl_xor_sync(0xffffffffu, s1, 2);
        if (sub < 2) {
            float v = (sub == 0 ? s0 : s1) + bias[r];
            float o;
            if (ACT == ACT_RELU)      o = fmaxf(v, 0.f);
            else if (ACT == ACT_ID)   o = v;
            else if (ACT == ACT_SIG)  o = 0.01f + 0.99f * (1.f / (1.f + expf(-v)));
            else { // ACT_AM : I + alpha * head
                const int ii = r >> 5, jj = r & 31;
                o = (ii == jj ? 1.f : 0.f) + alphav * v;
            }
            const int oidx = (r >> 5) * pitch + (r & 31);
            (sub == 0 ? out0 : out1)[oidx] = o;
        }
    }
}

__global__ void __launch_bounds__(NTHREADS, 1)
kf_kernel(const float* __restrict__ u,  const float* __restrict__ a,
          const float* __restrict__ W1, const float* __restrict__ b1,
          const float* __restrict__ W2, const float* __restrict__ b2,
          const float* __restrict__ WA, const float* __restrict__ bA,
          const float* __restrict__ WB, const float* __restrict__ bB,
          const float* __restrict__ WC, const float* __restrict__ bC,
          const float* __restrict__ Wnx, const float* __restrict__ bnx,
          const float* __restrict__ Wna, const float* __restrict__ bna,
          const float* __restrict__ alpha_p, float* __restrict__ out)
{
    extern __shared__ char smem_raw[];
    Smem* s = reinterpret_cast<Smem*>(smem_raw);

    const int tid = threadIdx.x;
    const int b0  = blockIdx.x * G;
    const float alphav = alpha_p[0];

    float* out_pm = out;                                        // [T][B][32]
    float* out_pc = out_pm + (size_t)TT * BB * XDIM;            // [T][B][32][32]
    float* out_qm = out_pc + (size_t)TT * BB * XDIM * XDIM;     // [T][B][32]
    float* out_qc = out_qm + (size_t)TT * BB * XDIM;            // [T][B][32][32]

    for (int t = 0; t < TT; ++t) {
        // ================= PRIOR =================
        if (t == 0) {
            // pm0 = 0, pc0 = I
            if (tid < G * 32) {
                const int g = tid >> 5, i = tid & 31;
                s->pm[g][i] = 0.f;
                out_pm[(((size_t)t * BB) + b0 + g) * XDIM + i] = 0.f;
            }
            for (int idx = tid; idx < G * 1024; idx += NTHREADS) {
                const int l = idx & 31, i = (idx >> 5) & 31, g = idx >> 10;
                const float v = (i == l) ? 1.f : 0.f;
                s->pc[g][i][l] = v;
                out_pc[(((size_t)t * BB) + b0 + g) * 1024 + i * 32 + l] = v;
            }
            __syncthreads();
        } else {
            if (tid < G * UDIM) {
                const int g = tid / UDIM, j = tid % UDIM;
                s->uvec[g][j] = u[(((size_t)(t - 1) * BB) + b0 + g) * UDIM + j];
            }
            // dyn(qm): h1 -> h2 -> Am, Bm, nx
            matvec_g2<32, ACT_RELU>(W1, b1, s->qm[0], s->qm[1], s->h1[0], s->h1[1], 256, 32, 0.f);
            __syncthreads();
            matvec_g2<256, ACT_RELU>(W2, b2, s->h1[0], s->h1[1], s->h2[0], s->h2[1], 256, 32, 0.f);
            __syncthreads();
            matvec_g2<256, ACT_AM >(WA, bA, s->h2[0], s->h2[1], &s->Am[0][0][0], &s->Am[1][0][0], 1024, 33, alphav);
            matvec_g2<256, ACT_ID >(WB, bB, s->h2[0], s->h2[1], &s->Bm[0][0][0], &s->Bm[1][0][0], 256, 32, 0.f);
            matvec_g2<256, ACT_SIG>(Wnx, bnx, s->h2[0], s->h2[1], s->nx[0], s->nx[1], 32, 32, 0.f);
            __syncthreads();
            // pm = Am@qm + Bm@u ; T1 = Am@qc
            if (tid < G * 32) {
                const int g = tid >> 5, i = tid & 31;
                float acc = 0.f;
                #pragma unroll
                for (int j = 0; j < 32; ++j) acc = fmaf(s->Am[g][i][j], s->qm[g][j], acc);
                #pragma unroll
                for (int j = 0; j < 8; ++j)  acc = fmaf(s->Bm[g][i][j], s->uvec[g][j], acc);
                s->pm[g][i] = acc;
                out_pm[(((size_t)t * BB) + b0 + g) * XDIM + i] = acc;
            }
            for (int idx = tid; idx < G * 1024; idx += NTHREADS) {
                const int k = idx & 31, i = (idx >> 5) & 31, g = idx >> 10;
                float acc = 0.f;
                #pragma unroll
                for (int j = 0; j < 32; ++j) acc = fmaf(s->Am[g][i][j], s->qc[g][j][k], acc);
                s->T1[g][i][k] = acc;
            }
            __syncthreads();
            // P = T1@Am^T + diag(nx)
            for (int idx = tid; idx < G * 1024; idx += NTHREADS) {
                const int l = idx & 31, i = (idx >> 5) & 31, g = idx >> 10;
                float acc = 0.f;
                #pragma unroll
                for (int k = 0; k < 32; ++k) acc = fmaf(s->T1[g][i][k], s->Am[g][l][k], acc);
                if (i == l) acc += s->nx[g][i];
                s->P[g][i][l] = acc;
            }
            __syncthreads();
            // pc = 0.5(P + P^T) + eps I ; write out
            for (int idx = tid; idx < G * 1024; idx += NTHREADS) {
                const int l = idx & 31, i = (idx >> 5) & 31, g = idx >> 10;
                float v = 0.5f * (s->P[g][i][l] + s->P[g][l][i]);
                if (i == l) v += EPSV;
                s->pc[g][i][l] = v;
                out_pc[(((size_t)t * BB) + b0 + g) * 1024 + i * 32 + l] = v;
            }
            __syncthreads();
        }

        // ================= POSTERIOR =================
        if (tid < G * ADIM) {
            const int g = tid / ADIM, j = tid % ADIM;
            s->avec[g][j] = a[(((size_t)t * BB) + b0 + g) * ADIM + j];
        }
        // dyn(pm): h1 -> h2 -> Cm, na
        matvec_g2<32, ACT_RELU>(W1, b1, s->pm[0], s->pm[1], s->h1[0], s->h1[1], 256, 32, 0.f);
        __syncthreads();
        matvec_g2<256, ACT_RELU>(W2, b2, s->h1[0], s->h1[1], s->h2[0], s->h2[1], 256, 32, 0.f);
        __syncthreads();
        matvec_g2<256, ACT_ID >(WC, bC, s->h2[0], s->h2[1], &s->Cm[0][0][0], &s->Cm[1][0][0], 768, 33, 0.f);
        matvec_g2<256, ACT_SIG>(Wna, bna, s->h2[0], s->h2[1], s->na[0], s->na[1], 24, 32, 0.f);
        __syncthreads();
        // T2 = Cm@pc ; T3 = pc@Cm^T ; innov ; Saug right half = I
        for (int idx = tid; idx < G * 768; idx += NTHREADS) {
            const int k = idx & 31, r = idx >> 5;
            const int i = r % 24, g = r / 24;
            float acc = 0.f;
            #pragma unroll
            for (int j = 0; j < 32; ++j) acc = fmaf(s->Cm[g][i][j], s->pc[g][j][k], acc);
            s->T2[g][i][k] = acc;
        }
        for (int idx = tid; idx < G * 768; idx += NTHREADS) {
            const int k = idx % 24, r = idx / 24;
            const int i = r & 31, g = r >> 5;
            float acc = 0.f;
            #pragma unroll
            for (int j = 0; j < 32; ++j) acc = fmaf(s->pc[g][i][j], s->Cm[g][k][j], acc);
            s->T3[g][i][k] = acc;
        }
        if (tid < G * 24) {
            const int g = tid / 24, i = tid % 24;
            float acc = s->avec[g][i];
            #pragma unroll
            for (int j = 0; j < 32; ++j) acc -= s->Cm[g][i][j] * s->pm[g][j];
            s->innov[g][i] = acc;
        }
        for (int idx = tid; idx < G * 576; idx += NTHREADS) {
            const int c = idx % 24, r = idx / 24;
            const int i = r % 24, g = r / 24;
            s->Saug[g][i][24 + c] = (i == c) ? 1.f : 0.f;
        }
        __syncthreads();
        // S = T2@Cm^T + diag(na)  (into Saug left half)
        for (int idx = tid; idx < G * 576; idx += NTHREADS) {
            const int l = idx % 24, r = idx / 24;
            const int i = r % 24, g = r / 24;
            float acc = 0.f;
            #pragma unroll
            for (int k = 0; k < 32; ++k) acc = fmaf(s->T2[g][i][k], s->Cm[g][l][k], acc);
            if (i == l) acc += s->na[g][i];
            s->Saug[g][i][l] = acc;
        }
        __syncthreads();
        // Gauss-Jordan inverse of S (symmetric PD, diag >= 0.01 => no pivoting needed)
        for (int col = 0; col < 24; ++col) {
            if (tid < G * 48) {
                const int g = tid / 48, c = tid % 48;
                s->rowbuf[g][c] = s->Saug[g][col][c];
            } else if (tid >= 128 && tid < 128 + G * 24) {
                const int q = tid - 128;
                const int g = q / 24, r2 = q % 24;
                s->colbuf[g][r2] = s->Saug[g][r2][col];
            } else if (tid >= 224 && tid < 224 + G) {
                s->pivinv[tid - 224] = 1.f / s->Saug[tid - 224][col][col];
            }
            __syncthreads();
            for (int idx = tid; idx < G * 24 * 48; idx += NTHREADS) {
                const int c = idx % 48, r2 = (idx / 48) % 24, g = idx / 1152;
                const float pv = s->pivinv[g];
                float val;
                if (r2 == col) val = s->rowbuf[g][c] * pv;
                else           val = s->Saug[g][r2][c] - (s->colbuf[g][r2] * pv) * s->rowbuf[g][c];
                s->Saug[g][r2][c] = val;
            }
            __syncthreads();
        }
        // Gmat = T3 @ Sinv
        for (int idx = tid; idx < G * 768; idx += NTHREADS) {
            const int l = idx % 24, r = idx / 24;
            const int i = r & 31, g = r >> 5;
            float acc = 0.f;
            #pragma unroll
            for (int k = 0; k < 24; ++k) acc = fmaf(s->T3[g][i][k], s->Saug[g][k][24 + l], acc);
            s->Gmat[g][i][l] = acc;
        }
        __syncthreads();
        // qm = pm + Gmat@innov ; P = pc - Gmat@T2
        if (tid < G * 32) {
            const int g = tid >> 5, i = tid & 31;
            float acc = s->pm[g][i];
            #pragma unroll
            for (int k = 0; k < 24; ++k) acc = fmaf(s->Gmat[g][i][k], s->innov[g][k], acc);
            s->qm[g][i] = acc;
            out_qm[(((size_t)t * BB) + b0 + g) * XDIM + i] = acc;
        }
        for (int idx = tid; idx < G * 1024; idx += NTHREADS) {
            const int l = idx & 31, i = (idx >> 5) & 31, g = idx >> 10;
            float acc = s->pc[g][i][l];
            #pragma unroll
            for (int k = 0; k < 24; ++k) acc -= s->Gmat[g][i][k] * s->T2[g][k][l];
            s->P[g][i][l] = acc;
        }
        __syncthreads();
        // qc = 0.5(P + P^T) + eps I ; write out
        for (int idx = tid; idx < G * 1024; idx += NTHREADS) {
            const int l = idx & 31, i = (idx >> 5) & 31, g = idx >> 10;
            float v = 0.5f * (s->P[g][i][l] + s->P[g][l][i]);
            if (i == l) v += EPSV;
            s->qc[g][i][l] = v;
            out_qc[(((size_t)t * BB) + b0 + g) * 1024 + i * 32 + l] = v;
        }
        __syncthreads();
    }
}

extern "C" void kernel_launch(void* const* d_in, const int* in_sizes, int n_in,
                              void* d_out, int out_size)
{
    (void)in_sizes; (void)n_in; (void)out_size;
    const float* u   = (const float*)d_in[0];
    const float* a   = (const float*)d_in[1];
    const float* W1  = (const float*)d_in[2];
    const float* b1  = (const float*)d_in[3];
    const float* W2  = (const float*)d_in[4];
    const float* b2  = (const float*)d_in[5];
    const float* WA  = (const float*)d_in[6];
    const float* bA  = (const float*)d_in[7];
    const float* WB  = (const float*)d_in[8];
    const float* bB  = (const float*)d_in[9];
    const float* WC  = (const float*)d_in[10];
    const float* bC  = (const float*)d_in[11];
    const float* Wnx = (const float*)d_in[12];
    const float* bnx = (const float*)d_in[13];
    const float* Wna = (const float*)d_in[14];
    const float* bna = (const float*)d_in[15];
    const float* alp = (const float*)d_in[16];
    float* out = (float*)d_out;

    cudaFuncSetAttribute(kf_kernel, cudaFuncAttributeMaxDynamicSharedMemorySize,
                         (int)sizeof(Smem));
    kf_kernel<<<BB / G, NTHREADS, sizeof(Smem)>>>(
        u, a, W1, b1, W2, b2, WA, bA, WB, bB, WC, bC, Wnx, bnx, Wna, bna, alp, out);
}